// round 11
// baseline (speedup 1.0000x reference)
#include <cuda_runtime.h>
#include <math.h>

#define N 2048
#define K 8
#define FN 16
#define O 32

#define TJ 128   // j-columns per block
#define TI 64    // i-rows per block

// Scratch (allocation-free): __device__ globals
__device__ float g_rinv[N];
__device__ float g_agg[N * K];
__device__ float g_col[N];

// Kernel 1: barrier-free warp-per-row row sums + scratch zero.
// Each warp owns one row: 16 float4 loads per lane, pure shuffle reduce.
// Measured 7.33us; shape-invariant floor (~5us fixed + ~2.5us transfer),
// three configurations (scalar strided, block-per-row, warp-per-row) all
// converge to ~7.3-7.4us -> do not re-attack.
__global__ void __launch_bounds__(128) k_rowsum(const float* __restrict__ adj) {
    int warp_g = (blockIdx.x * blockDim.x + threadIdx.x) >> 5;  // 0..2047
    int lane   = threadIdx.x & 31;
    int row    = warp_g;

    const float4* r = (const float4*)(adj + (size_t)row * N);  // 512 float4s

    float s = 0.0f;
    #pragma unroll
    for (int u = 0; u < 16; ++u) {
        float4 v = __ldg(r + lane + 32 * u);
        s += (v.x + v.y) + (v.z + v.w);
    }

    #pragma unroll
    for (int off = 16; off; off >>= 1) s += __shfl_xor_sync(0xFFFFFFFFu, s, off);

    // Zero this row's accumulator scratch (lanes 0..7 -> agg, lane 8 -> col)
    if (lane < K) g_agg[row * K + lane] = 0.0f;
    else if (lane == K) g_col[row] = 0.0f;

    if (lane == 0) {
        float inv = 1.0f / s;
        if (!isfinite(inv)) inv = 0.0f;
        g_rinv[row] = inv;
    }
}

// Kernel 2: main accumulation over E (the 128 MiB read). MEASURED-BEST form:
// plain cached LDG.128 on E (NO __ldcs: evict-first measured +12.5us — it
// defeats L2 sector promotion on the stream), __ldg on adj, unroll 4.
// Accum variant table (us, by subtraction): u4-nocs 22.1 | u8-cs 24.6 |
// u16-cs 31.3 | u4-cs 34.6.  22.1us for ~144MiB = ~6.5TB/s ~= LTS ceiling.
__global__ void __launch_bounds__(256) k_accum(const float* __restrict__ E,
                                               const float* __restrict__ adj) {
    const int nJB = N / TJ;                 // 16
    int jb = blockIdx.x % nJB;
    int ib = blockIdx.x / nJB;
    int j0 = jb * TJ;
    int i0 = ib * TI;

    int tid = threadIdx.x;                  // 0..255
    int e0  = tid * 4;                      // element in [0, TJ*K)
    int jl  = e0 >> 3;                      // local j (= tid/2), two threads share a j
    int k0  = e0 & 7;                       // 0 or 4

    __shared__ float s_rinv[TI];
    if (tid < TI) s_rinv[tid] = g_rinv[i0 + tid];
    __syncthreads();

    float4 acc = make_float4(0.f, 0.f, 0.f, 0.f);
    float colp = 0.0f;

    const float* Ebase = E + ((size_t)i0 * N + j0) * K + e0;
    const float* Abase = adj + (size_t)i0 * N + j0 + jl;

    #pragma unroll 4
    for (int ii = 0; ii < TI; ++ii) {
        float s = s_rinv[ii] * __ldg(Abase + (size_t)ii * N);
        float4 ev = *(const float4*)(Ebase + (size_t)ii * N * K);
        acc.x = fmaf(s, ev.x, acc.x);
        acc.y = fmaf(s, ev.y, acc.y);
        acc.z = fmaf(s, ev.z, acc.z);
        acc.w = fmaf(s, ev.w, acc.w);
        if (k0 == 0) colp += s;
    }

    int j = j0 + jl;
    float* ag = &g_agg[j * K + k0];
    atomicAdd(ag + 0, acc.x);
    atomicAdd(ag + 1, acc.y);
    atomicAdd(ag + 2, acc.z);
    atomicAdd(ag + 3, acc.w);
    if (k0 == 0) atomicAdd(&g_col[j], colp);
}

// Kernel 3: epilogue. Warp per output row j, lane = output col o.
// out[j,o] = sum_k agg[j,k]*W[k,o] + col[j] * sum_f nf[j,f]*W[K+f,o]
__global__ void k_epilogue(const float* __restrict__ nf,
                           const float* __restrict__ W,
                           float* __restrict__ out) {
    int gtid = blockIdx.x * blockDim.x + threadIdx.x;
    int j = gtid >> 5;
    int o = gtid & 31;
    if (j >= N) return;

    float r = 0.0f;
    #pragma unroll
    for (int k = 0; k < K; ++k)
        r = fmaf(g_agg[j * K + k], __ldg(&W[k * O + o]), r);

    float nn = 0.0f;
    #pragma unroll
    for (int f = 0; f < FN; ++f)
        nn = fmaf(__ldg(&nf[j * FN + f]), __ldg(&W[(K + f) * O + o]), nn);

    out[j * O + o] = r + g_col[j] * nn;
}

extern "C" void kernel_launch(void* const* d_in, const int* in_sizes, int n_in,
                              void* d_out, int out_size) {
    const float* node_features = (const float*)d_in[0];   // (N, FN)
    const float* edge_feat     = (const float*)d_in[1];   // (N, N, K)
    const float* adj           = (const float*)d_in[2];   // (N, N)
    const float* weight        = (const float*)d_in[3];   // (K+FN, O)
    float* out = (float*)d_out;                           // (N, O)

    // 1) row sums + scratch zero: warp per row, 2048 warps
    k_rowsum<<<N / 4, 128>>>(adj);
    // 2) main accumulation: (N/TJ)*(N/TI) = 16*32 = 512 blocks
    k_accum<<<(N / TJ) * (N / TI), 256>>>(edge_feat, adj);
    // 3) epilogue: 2048 rows * 32 cols / 256 = 256 blocks
    k_epilogue<<<256, 256>>>(node_features, weight, out);
}

// round 14
// speedup vs baseline: 1.4654x; 1.4654x over previous
#include <cuda_runtime.h>
#include <math.h>

#define N 2048
#define K 8
#define FN 16
#define O 32

#define TJ 128   // j-columns per block
#define TI 64    // i-rows per block

// Scratch (allocation-free): __device__ globals
__device__ float g_rinv[N];
__device__ float g_agg[N * K];
__device__ float g_col[N];

// Kernel 1: barrier-free warp-per-row row sums + scratch zero.
// Each warp owns one row: 16 float4 loads per lane, pure shuffle reduce.
// Measured 6.94us — best of three shapes tried (12.0 scalar, 7.4 block/row);
// remaining cost is a shape-invariant per-kernel floor. Do not re-attack.
__global__ void __launch_bounds__(128) k_rowsum(const float* __restrict__ adj) {
    int warp_g = (blockIdx.x * blockDim.x + threadIdx.x) >> 5;  // 0..2047
    int lane   = threadIdx.x & 31;
    int row    = warp_g;

    const float4* r = (const float4*)(adj + (size_t)row * N);  // 512 float4s

    float s = 0.0f;
    #pragma unroll
    for (int u = 0; u < 16; ++u) {
        float4 v = __ldg(r + lane + 32 * u);
        s += (v.x + v.y) + (v.z + v.w);
    }

    #pragma unroll
    for (int off = 16; off; off >>= 1) s += __shfl_xor_sync(0xFFFFFFFFu, s, off);

    // Zero this row's accumulator scratch (lanes 0..7 -> agg, lane 8 -> col)
    if (lane < K) g_agg[row * K + lane] = 0.0f;
    else if (lane == K) g_col[row] = 0.0f;

    if (lane == 0) {
        float inv = 1.0f / s;
        if (!isfinite(inv)) inv = 0.0f;
        g_rinv[row] = inv;
    }
}

// Kernel 2: main accumulation over E (the 128 MiB read).
// MEASURED-BEST, reproduced twice: unroll 8 + __ldcs on E.
// Corrected accum table (us, by subtraction):
//   u8+ldcs 22.0 / 24.6  |  u16+ldcs 31.3  |  u4+ldcs 34.6  |  u4 plain 39.7
// u4 is MLP-starved vs ~577cyc DRAM latency; u16 hits the cross-CTA
// L1tex-queue spread regime; u8 is the sweet spot. __ldcs (evict-first)
// HELPS the 128MiB single-use stream (34.6 vs 39.7 at fixed u4).
__global__ void __launch_bounds__(256) k_accum(const float* __restrict__ E,
                                               const float* __restrict__ adj) {
    const int nJB = N / TJ;                 // 16
    int jb = blockIdx.x % nJB;
    int ib = blockIdx.x / nJB;
    int j0 = jb * TJ;
    int i0 = ib * TI;

    int tid = threadIdx.x;                  // 0..255
    int e0  = tid * 4;                      // element in [0, TJ*K)
    int jl  = e0 >> 3;                      // local j (= tid/2), two threads share a j
    int k0  = e0 & 7;                       // 0 or 4

    __shared__ float s_rinv[TI];
    if (tid < TI) s_rinv[tid] = g_rinv[i0 + tid];
    __syncthreads();

    float4 acc = make_float4(0.f, 0.f, 0.f, 0.f);
    float colp = 0.0f;

    const float* Ebase = E + ((size_t)i0 * N + j0) * K + e0;
    const float* Abase = adj + (size_t)i0 * N + j0 + jl;

    #pragma unroll 8
    for (int ii = 0; ii < TI; ++ii) {
        float s = s_rinv[ii] * __ldg(Abase + (size_t)ii * N);
        float4 ev = __ldcs((const float4*)(Ebase + (size_t)ii * N * K));
        acc.x = fmaf(s, ev.x, acc.x);
        acc.y = fmaf(s, ev.y, acc.y);
        acc.z = fmaf(s, ev.z, acc.z);
        acc.w = fmaf(s, ev.w, acc.w);
        if (k0 == 0) colp += s;
    }

    int j = j0 + jl;
    float* ag = &g_agg[j * K + k0];
    atomicAdd(ag + 0, acc.x);
    atomicAdd(ag + 1, acc.y);
    atomicAdd(ag + 2, acc.z);
    atomicAdd(ag + 3, acc.w);
    if (k0 == 0) atomicAdd(&g_col[j], colp);
}

// Kernel 3: epilogue. Warp per output row j, lane = output col o.
// out[j,o] = sum_k agg[j,k]*W[k,o] + col[j] * sum_f nf[j,f]*W[K+f,o]
__global__ void k_epilogue(const float* __restrict__ nf,
                           const float* __restrict__ W,
                           float* __restrict__ out) {
    int gtid = blockIdx.x * blockDim.x + threadIdx.x;
    int j = gtid >> 5;
    int o = gtid & 31;
    if (j >= N) return;

    float r = 0.0f;
    #pragma unroll
    for (int k = 0; k < K; ++k)
        r = fmaf(g_agg[j * K + k], __ldg(&W[k * O + o]), r);

    float nn = 0.0f;
    #pragma unroll
    for (int f = 0; f < FN; ++f)
        nn = fmaf(__ldg(&nf[j * FN + f]), __ldg(&W[(K + f) * O + o]), nn);

    out[j * O + o] = r + g_col[j] * nn;
}

extern "C" void kernel_launch(void* const* d_in, const int* in_sizes, int n_in,
                              void* d_out, int out_size) {
    const float* node_features = (const float*)d_in[0];   // (N, FN)
    const float* edge_feat     = (const float*)d_in[1];   // (N, N, K)
    const float* adj           = (const float*)d_in[2];   // (N, N)
    const float* weight        = (const float*)d_in[3];   // (K+FN, O)
    float* out = (float*)d_out;                           // (N, O)

    // 1) row sums + scratch zero: warp per row, 2048 warps
    k_rowsum<<<N / 4, 128>>>(adj);
    // 2) main accumulation: (N/TJ)*(N/TI) = 16*32 = 512 blocks
    k_accum<<<(N / TJ) * (N / TI), 256>>>(edge_feat, adj);
    // 3) epilogue: 2048 rows * 32 cols / 256 = 256 blocks
    k_epilogue<<<256, 256>>>(node_features, weight, out);
}